// round 12
// baseline (speedup 1.0000x reference)
#include <cuda_runtime.h>

// Problem constants
#define DM    100
#define NSDK  2048
#define ROWS  1024        // SZ_B * L
#define DI_   400
#define KSPLIT 8
#define PART_STRIDE (ROWS * DM)
#define LOG2E 1.44269504088896340736f
#define NSB   32768       // sub-blocks = SZ_B * NS

// Scratch (device globals — no allocation)
__device__ float g_qkv[3u * 2097152u];        // [p][sb][w*32+h], affine applied
__device__ float g_att[ROWS * NSDK];          // attention output (tf32 bits)
__device__ float g_part[KSPLIT * PART_STRIDE];// fc split-K partials

// ---------------------------------------------------------------------------
// helpers
// ---------------------------------------------------------------------------
__device__ __forceinline__ float ex2(float x) {     // raw MUFU.EX2
    float y;
    asm("ex2.approx.f32 %0, %1;" : "=f"(y) : "f"(x));
    return y;
}

__device__ __forceinline__ unsigned f2tf(float v) {
    unsigned r;
    asm("cvt.rna.tf32.f32 %0, %1;" : "=r"(r) : "f"(v));
    return r;
}

__device__ __forceinline__ void cvt4_inplace(float* p) {
    float4 v = *(float4*)p;
    unsigned u0 = f2tf(v.x), u1 = f2tf(v.y), u2 = f2tf(v.z), u3 = f2tf(v.w);
    uint4 w = make_uint4(u0, u1, u2, u3);
    *(uint4*)p = w;
}

__device__ __forceinline__ void mma_tf32(float c[4],
                                         unsigned a0, unsigned a1, unsigned a2, unsigned a3,
                                         unsigned b0, unsigned b1) {
    asm("mma.sync.aligned.m16n8k8.row.col.f32.tf32.tf32.f32 "
        "{%0,%1,%2,%3},{%4,%5,%6,%7},{%8,%9},{%0,%1,%2,%3};"
        : "+f"(c[0]), "+f"(c[1]), "+f"(c[2]), "+f"(c[3])
        : "r"(a0), "r"(a1), "r"(a2), "r"(a3), "r"(b0), "r"(b1));
}

__device__ __forceinline__ unsigned sa(const void* p) {
    return (unsigned)__cvta_generic_to_shared(p);
}
__device__ __forceinline__ void cp16(unsigned d, const void* s) {
    asm volatile("cp.async.ca.shared.global [%0], [%1], 16;" :: "r"(d), "l"(s));
}
__device__ __forceinline__ void cp16z(unsigned d, const void* s, int srcbytes) {
    asm volatile("cp.async.ca.shared.global [%0], [%1], 16, %2;"
                 :: "r"(d), "l"(s), "r"(srcbytes));
}
#define CP_COMMIT    asm volatile("cp.async.commit_group;")
#define CP_WAIT_1    asm volatile("cp.async.wait_group 1;")
#define CP_WAIT_0    asm volatile("cp.async.wait_group 0;")
#define CP_WAIT_ALL  asm volatile("cp.async.wait_all;")

// ---------------------------------------------------------------------------
// K1a: QKV projection GEMM. K=100 smem-resident, tf32 in place.
// Writes affine-applied Q/K/V to g_qkv[p][sb][w*32+h] (f32).
// Block 384 thr (12 warps): warp = proj (w>>2) x m-slice ((w&3)*16).
// grid (64 ns, 16 rowtiles). Dynamic smem 69120 B.
// ---------------------------------------------------------------------------
__global__ __launch_bounds__(384) void qkv_gemm(
        const float* __restrict__ edges,
        const float* __restrict__ wq, const float* __restrict__ bq,
        const float* __restrict__ wk, const float* __restrict__ bk,
        const float* __restrict__ wv, const float* __restrict__ bv,
        const float* __restrict__ qcw, const float* __restrict__ qcb,
        const float* __restrict__ kcw, const float* __restrict__ kcb,
        const float* __restrict__ vcw, const float* __restrict__ vcb)
{
    extern __shared__ float smem[];
    float* A = smem;                 // [64][108]
    float* B = smem + 64 * 108;      // [96][108]

    const int t    = threadIdx.x;
    const int lane = t & 31;
    const int wid  = t >> 5;
    const int tig  = lane & 3;
    const int gid  = lane >> 2;

    const int ns   = blockIdx.x;
    const int row0 = blockIdx.y * 64;

    const int pw = wid >> 2;
    const int m0 = (wid & 3) * 16;

    for (int idx = t; idx < 1600; idx += 384) {
        int r = idx / 25, q = idx - r * 25;
        cp16(sa(A + r * 108 + q * 4), edges + (row0 + r) * DM + q * 4);
    }
    for (int idx = t; idx < 2400; idx += 384) {
        int rr = idx / 25, q = idx - rr * 25;
        int p = rr >> 5, n = rr & 31;
        const float* W = (p == 0) ? wq : (p == 1) ? wk : wv;
        cp16(sa(B + rr * 108 + q * 4), W + (ns * 32 + n) * DM + q * 4);
    }
    CP_COMMIT; CP_WAIT_ALL;

    for (int idx = t; idx < 1600; idx += 384) {
        int r = idx / 25, q = idx - r * 25;
        cvt4_inplace(A + r * 108 + q * 4);
    }
    for (int idx = t; idx < 2400; idx += 384) {
        int rr = idx / 25, q = idx - rr * 25;
        cvt4_inplace(B + rr * 108 + q * 4);
    }
    for (int idx = t; idx < 160; idx += 384) {
        float* ptr = smem + idx * 108 + 100;
        ptr[0] = 0.0f; ptr[1] = 0.0f; ptr[2] = 0.0f; ptr[3] = 0.0f;
    }
    __syncthreads();

    const unsigned* Au = (const unsigned*)A;
    const unsigned* Bu = (const unsigned*)B;

    float acc[4][4] = {};
    #pragma unroll
    for (int ks = 0; ks < 13; ks++) {
        const int k0 = ks * 8;
        unsigned a0 = Au[(m0 + gid) * 108 + k0 + tig];
        unsigned a1 = Au[(m0 + gid + 8) * 108 + k0 + tig];
        unsigned a2 = Au[(m0 + gid) * 108 + k0 + tig + 4];
        unsigned a3 = Au[(m0 + gid + 8) * 108 + k0 + tig + 4];
        #pragma unroll
        for (int j = 0; j < 4; j++) {
            const int brow = pw * 32 + j * 8 + gid;
            unsigned b0 = Bu[brow * 108 + k0 + tig];
            unsigned b1 = Bu[brow * 108 + k0 + tig + 4];
            mma_tf32(acc[j], a0, a1, a2, a3, b0, b1);
        }
    }

    // epilogue: affine + bias -> g_qkv[p][sb][w*32 + h]
    // element (row grow, col) with col even: h = 16*(grow&1) + col/2;
    // (col, w=0) and (col+1, w=1).
    {
        const float scale = (pw == 0) ? *qcw : (pw == 1) ? *kcw : *vcw;
        const float shift = (pw == 0) ? *qcb : (pw == 1) ? *kcb : *vcb;
        const float* bias = (pw == 0) ? bq : (pw == 1) ? bk : bv;
        float* outq = g_qkv + (unsigned)pw * 2097152u;

        #pragma unroll
        for (int j = 0; j < 4; j++) {
            const int col = j * 8 + 2 * tig;           // even
            const float b0v = bias[ns * 32 + col];
            const float b1v = bias[ns * 32 + col + 1];
            #pragma unroll
            for (int i = 0; i < 2; i++) {
                const int grow  = row0 + m0 + gid + i * 8;
                const int batch = grow >> 1;
                const int h     = 16 * (grow & 1) + (col >> 1);
                const unsigned dst = ((unsigned)batch * 64u + ns) * 64u;
                outq[dst + h]      = fmaf(scale, acc[j][2 * i] + b0v, shift);
                outq[dst + 32 + h] = fmaf(scale, acc[j][2 * i + 1] + b1v, shift);
            }
        }
    }
}

// ---------------------------------------------------------------------------
// K1b: attention. 256 thr, 8 sub-blocks/block (warp = one sub-block).
// Pair-blocked softmax (items h0 and h0+16), 1 pair/thread. smem 6 KB.
// grid 4096. Outputs to g_att (tf32 bits), coalesced 128B stores.
// ---------------------------------------------------------------------------
__global__ __launch_bounds__(256) void attn_kernel()
{
    __shared__ float sm[8][3][64];     // [sub][proj][flat]

    const int t    = threadIdx.x;
    const int sub  = t >> 5;
    const int lane = t & 31;
    const int sb0  = blockIdx.x * 8;

    // load 8 sub-blocks x 3 projections x 64 floats = 384 float4s
    for (int idx = t; idx < 384; idx += 256) {
        int s  = idx / 48;
        int rm = idx - s * 48;
        int p  = rm >> 4;
        int q4 = rm & 15;
        cp16(sa(&sm[s][p][q4 * 4]),
             g_qkv + ((unsigned)p * 2097152u + (unsigned)(sb0 + s) * 64u) + q4 * 4);
    }
    CP_COMMIT; CP_WAIT_ALL;
    __syncthreads();

    const float* sq = sm[sub][0];
    const float* sk = sm[sub][1];
    const float* sv = sm[sub][2];

    const int w  = lane >> 4;
    const int h0 = lane & 15;
    const int wb = w * 32;

    const float q0 = sq[wb + h0] * LOG2E;
    const float q1 = sq[wb + h0 + 16] * LOG2E;
    const float* Kw = sk + wb;
    const float* Vw = sv + wb;

    float Z0 = 0.0f, A0 = 0.0f, Z1 = 0.0f, A1 = 0.0f;
    #pragma unroll
    for (int c = 0; c < 8; c++) {
        float4 k4 = *(const float4*)(Kw + 4 * c);   // warp-broadcast (2 addrs)
        float4 v4 = *(const float4*)(Vw + 4 * c);
        float e;
        e = ex2(q0 * k4.x); Z0 += e; A0 = fmaf(e, v4.x, A0);
        e = ex2(q1 * k4.x); Z1 += e; A1 = fmaf(e, v4.x, A1);
        e = ex2(q0 * k4.y); Z0 += e; A0 = fmaf(e, v4.y, A0);
        e = ex2(q1 * k4.y); Z1 += e; A1 = fmaf(e, v4.y, A1);
        e = ex2(q0 * k4.z); Z0 += e; A0 = fmaf(e, v4.z, A0);
        e = ex2(q1 * k4.z); Z1 += e; A1 = fmaf(e, v4.z, A1);
        e = ex2(q0 * k4.w); Z0 += e; A0 = fmaf(e, v4.w, A0);
        e = ex2(q1 * k4.w); Z1 += e; A1 = fmaf(e, v4.w, A1);
    }

    // in-W terms + diag removal (cross loop included g==h once).
    const float k00 = sk[h0];
    const float k01 = sk[32 + h0];
    const float v00 = sv[h0];
    const float v01 = sv[32 + h0];
    const float k10 = sk[h0 + 16];
    const float k11 = sk[32 + h0 + 16];
    const float v10 = sv[h0 + 16];
    const float v11 = sv[32 + h0 + 16];

    const float e00 = ex2(q0 * k00);
    const float e01 = ex2(q0 * k01);
    const float e10 = ex2(q1 * k10);
    const float e11 = ex2(q1 * k11);

    const float pd0 = w ? e01 : e00;
    const float vd0 = w ? v01 : v00;
    const float pd1 = w ? e11 : e10;
    const float vd1 = w ? v11 : v10;

    Z0 = Z0 - pd0 + e00 + e01;
    A0 = A0 - pd0 * vd0 + e00 * v00 + e01 * v01;
    Z1 = Z1 - pd1 + e10 + e11;
    A1 = A1 - pd1 * vd1 + e10 * v10 + e11 * v11;

    const float o0 = __fdividef(A0, Z0);
    const float o1 = __fdividef(A1, Z1);

    const int sb    = sb0 + sub;
    const int batch = sb >> 6;
    const int ns    = sb & 63;
    const int dk    = 2 * h0 + w;
    unsigned* g_att_u = (unsigned*)g_att;
    g_att_u[(batch * 2) * NSDK + ns * 32 + dk]     = f2tf(o0);
    g_att_u[(batch * 2 + 1) * NSDK + ns * 32 + dk] = f2tf(o1);
}

// ---------------------------------------------------------------------------
// K2: fc GEMM split-K (tf32), double-buffered cp.async. A (g_att) arrives
// already tf32-rounded -> only B needs in-place conversion.
// 256 threads (8 warps: 4M x 2N). Tile 64(M) x 112(N), 4 chunks of K=64.
// grid (16, 8). Dynamic smem 95744 B.
// ---------------------------------------------------------------------------
__global__ __launch_bounds__(256) void fc_tc(const float* __restrict__ fcw)
{
    extern __shared__ float smem[];
    // buf b at offset b*11968: A[64][68] then B[112][68]

    const int t    = threadIdx.x;
    const int lane = t & 31;
    const int wid  = t >> 5;
    const int tig  = lane & 3;
    const int gid  = lane >> 2;

    const int row0 = blockIdx.x * 64;
    const int ks   = blockIdx.y;

    const int wm0 = (wid >> 1) * 16;
    const int wn0 = (wid & 1) * 56;

    float acc[7][4] = {};

    auto load_chunk = [&](int c, int buf) {
        const int kb = ks * 256 + c * 64;
        float* A = smem + buf * 11968;
        float* B = A + 4352;
        for (int idx = t; idx < 1024; idx += 256) {
            int r = idx >> 4, q = idx & 15;
            cp16(sa(A + r * 68 + q * 4), g_att + (row0 + r) * NSDK + kb + q * 4);
        }
        for (int idx = t; idx < 1792; idx += 256) {
            int r = idx >> 4, q = idx & 15;
            int rc = (r < DM) ? r : (DM - 1);
            cp16z(sa(B + r * 68 + q * 4), fcw + rc * NSDK + kb + q * 4,
                  (r < DM) ? 16 : 0);
        }
        CP_COMMIT;
    };

    load_chunk(0, 0);

    for (int c = 0; c < 4; c++) {
        if (c < 3) load_chunk(c + 1, (c + 1) & 1);
        if (c < 3) { CP_WAIT_1; } else { CP_WAIT_0; }

        float* Af = smem + (c & 1) * 11968;
        float* Bf = Af + 4352;

        // B conversion only (A already tf32 bits)
        for (int idx = t; idx < 1792; idx += 256) {
            int r = idx >> 4, q = idx & 15;
            cvt4_inplace(Bf + r * 68 + q * 4);
        }
        __syncthreads();

        const unsigned* A = (const unsigned*)Af;
        const unsigned* B = (const unsigned*)Bf;

        #pragma unroll
        for (int kss = 0; kss < 8; kss++) {
            const int k0 = kss * 8;
            unsigned a0 = A[(wm0 + gid) * 68 + k0 + tig];
            unsigned a1 = A[(wm0 + gid + 8) * 68 + k0 + tig];
            unsigned a2 = A[(wm0 + gid) * 68 + k0 + tig + 4];
            unsigned a3 = A[(wm0 + gid + 8) * 68 + k0 + tig + 4];
            #pragma unroll
            for (int j = 0; j < 7; j++) {
                const int brow = wn0 + j * 8 + gid;
                unsigned b0 = B[brow * 68 + k0 + tig];
                unsigned b1 = B[brow * 68 + k0 + tig + 4];
                mma_tf32(acc[j], a0, a1, a2, a3, b0, b1);
            }
        }
        __syncthreads();
    }

    #pragma unroll
    for (int j = 0; j < 7; j++) {
        const int col = wn0 + j * 8 + 2 * tig;
        if (col < DM) {
            int r0 = row0 + wm0 + gid;
            *(float2*)&g_part[ks * PART_STRIDE + r0 * DM + col] =
                make_float2(acc[j][0], acc[j][1]);
            *(float2*)&g_part[ks * PART_STRIDE + (r0 + 8) * DM + col] =
                make_float2(acc[j][2], acc[j][3]);
        }
    }
}

// ---------------------------------------------------------------------------
// K3: FUSED tail: partials-reduce + LN1 + MLP-l1(relu) + MLP-l2 + LN2 -> out.
// 16 rows/block, grid 64, 256 threads (8 warps). All intermediates in smem.
// ---------------------------------------------------------------------------
__global__ __launch_bounds__(256) void mlp_fused(
        const float* __restrict__ edges, const float* __restrict__ fcb,
        const float* __restrict__ ln1g,  const float* __restrict__ ln1b,
        const float* __restrict__ w1,    const float* __restrict__ w1b,
        const float* __restrict__ w2,    const float* __restrict__ w2b,
        const float* __restrict__ ln2g,  const float* __restrict__ ln2b,
        float* __restrict__ outp)
{
    extern __shared__ float smem[];
    float* xs  = smem;            // [16][108]  LN1 output (k-pad zeroed)
    float* hs  = smem + 1728;     // [16][420]  hidden (cols 400..415 zeroed)
    float* sR0 = smem + 8448;
    float* sR1 = smem + 30912;

    const int t    = threadIdx.x;
    const int lane = t & 31;
    const int wid  = t >> 5;
    const int tig  = lane & 3;
    const int gid  = lane >> 2;
    const int row0 = blockIdx.x * 16;

    auto cp_w1 = [&](int chunk, float* R) {
        const int rows = chunk ? 192 : 208;
        const int base = chunk * 208;
        for (int idx = t; idx < rows * 26; idx += 256) {
            int r = idx / 26, q = idx - r * 26;
            if (q < 25)
                cp16(sa(R + r * 108 + q * 4), w1 + (base + r) * DM + q * 4);
            else
                cp16z(sa(R + r * 108 + 100), w1, 0);
        }
        CP_COMMIT;
    };

    auto cp_w2 = [&](int chunk, float* R) {
        const int kbase = chunk * 208;
        for (int idx = t; idx < 104 * 52; idx += 256) {
            int r = idx / 52, q = idx - r * 52;
            int k = kbase + q * 4;
            int ok = (r < DM) && (k + 4 <= DI_);
            cp16z(sa(R + r * 212 + q * 4),
                  w2 + (ok ? r * DI_ + k : 0), ok ? 16 : 0);
        }
        CP_COMMIT;
    };

    cp_w1(0, sR0);                                   // G0

    for (int idx = t; idx < 1600; idx += 256) {
        int r = idx / 100, c = idx - r * 100;
        int grow = row0 + r;
        float v = fcb[c] + edges[grow * DM + c];
        #pragma unroll
        for (int s = 0; s < KSPLIT; s++)
            v += g_part[s * PART_STRIDE + grow * DM + c];
        xs[r * 108 + c] = v;
    }
    __syncthreads();

    if (t < 64) {
        const int r = t >> 2, s4 = t & 3;
        float vals[25];
        float sum = 0.0f;
        #pragma unroll
        for (int j = 0; j < 25; j++) {
            float v = xs[r * 108 + s4 + 4 * j];
            vals[j] = v;  sum += v;
        }
        sum += __shfl_xor_sync(0xffffffffu, sum, 1);
        sum += __shfl_xor_sync(0xffffffffu, sum, 2);
        const float mean = sum * (1.0f / DM);
        float v2 = 0.0f;
        #pragma unroll
        for (int j = 0; j < 25; j++) {
            float d = vals[j] - mean;
            v2 = fmaf(d, d, v2);
        }
        v2 += __shfl_xor_sync(0xffffffffu, v2, 1);
        v2 += __shfl_xor_sync(0xffffffffu, v2, 2);
        const float inv = rsqrtf(v2 * (1.0f / DM) + 1e-5f);
        #pragma unroll
        for (int j = 0; j < 25; j++) {
            int c = s4 + 4 * j;
            xs[r * 108 + c] = (vals[j] - mean) * inv * ln1g[c] + ln1b[c];
        }
        if (s4 == 0) {
            xs[r * 108 + 100] = 0.0f; xs[r * 108 + 101] = 0.0f;
            xs[r * 108 + 102] = 0.0f; xs[r * 108 + 103] = 0.0f;
        }
    }

    cp_w1(1, sR1);                                   // G1
    CP_WAIT_1; __syncthreads();                      // G0 done

    auto layer1_chunk = [&](int chunk, const float* R) {
        const int nfr = chunk ? 24 : 26;
        const int nmy = (nfr - wid + 7) >> 3;
        const int nbg = chunk * 208;
        float acc[4][4] = {};
        #pragma unroll
        for (int ks = 0; ks < 13; ks++) {
            const int k0 = ks * 8;
            unsigned a0 = f2tf(xs[gid * 108 + k0 + tig]);
            unsigned a1 = f2tf(xs[(gid + 8) * 108 + k0 + tig]);
            unsigned a2 = f2tf(xs[gid * 108 + k0 + tig + 4]);
            unsigned a3 = f2tf(xs[(gid + 8) * 108 + k0 + tig + 4]);
            #pragma unroll
            for (int j = 0; j < 4; j++) {
                if (j < nmy) {
                    int brow = (wid + 8 * j) * 8 + gid;
                    unsigned b0 = f2tf(R[brow * 108 + k0 + tig]);
                    unsigned b1 = f2tf(R[brow * 108 + k0 + tig + 4]);
                    mma_tf32(acc[j], a0, a1, a2, a3, b0, b1);
                }
            }
        }
        #pragma unroll
        for (int j = 0; j < 4; j++) {
            if (j < nmy) {
                int cg = nbg + (wid + 8 * j) * 8 + 2 * tig;
                float bb0 = w1b[cg], bb1 = w1b[cg + 1];
                hs[gid * 420 + cg]           = fmaxf(acc[j][0] + bb0, 0.0f);
                hs[gid * 420 + cg + 1]       = fmaxf(acc[j][1] + bb1, 0.0f);
                hs[(gid + 8) * 420 + cg]     = fmaxf(acc[j][2] + bb0, 0.0f);
                hs[(gid + 8) * 420 + cg + 1] = fmaxf(acc[j][3] + bb1, 0.0f);
            }
        }
    };

    layer1_chunk(0, sR0);
    __syncthreads();
    cp_w2(0, sR0);                                   // G2
    CP_WAIT_1; __syncthreads();                      // G1 done
    layer1_chunk(1, sR1);
    {
        int r = t >> 4, c = 400 + (t & 15);
        hs[r * 420 + c] = 0.0f;
    }
    __syncthreads();
    cp_w2(1, sR1);                                   // G3
    CP_WAIT_1; __syncthreads();                      // G2 done

    const int nmy2 = (wid < 5) ? 2 : 1;
    float l2acc[2][4] = {};
    auto layer2_chunk = [&](int chunk, const float* R) {
        #pragma unroll 2
        for (int ks = 0; ks < 26; ks++) {
            const int k0 = ks * 8;
            const int kk = chunk * 208 + k0;
            unsigned a0 = f2tf(hs[gid * 420 + kk + tig]);
            unsigned a1 = f2tf(hs[(gid + 8) * 420 + kk + tig]);
            unsigned a2 = f2tf(hs[gid * 420 + kk + tig + 4]);
            unsigned a3 = f2tf(hs[(gid + 8) * 420 + kk + tig + 4]);
            #pragma unroll
            for (int j = 0; j < 2; j++) {
                if (j < nmy2) {
                    int brow = (wid + 8 * j) * 8 + gid;
                    unsigned b0 = f2tf(R[brow * 212 + k0 + tig]);
                    unsigned b1 = f2tf(R[brow * 212 + k0 + tig + 4]);
                    mma_tf32(l2acc[j], a0, a1, a2, a3, b0, b1);
                }
            }
        }
    };

    layer2_chunk(0, sR0);
    CP_WAIT_0; __syncthreads();                      // G3 done
    layer2_chunk(1, sR1);

    __syncthreads();
    float* ys = sR0;                                 // [16][104]
    #pragma unroll
    for (int j = 0; j < 2; j++) {
        if (j < nmy2) {
            int col = (wid + 8 * j) * 8 + 2 * tig;
            ys[gid * 104 + col]           = l2acc[j][0];
            ys[gid * 104 + col + 1]       = l2acc[j][1];
            ys[(gid + 8) * 104 + col]     = l2acc[j][2];
            ys[(gid + 8) * 104 + col + 1] = l2acc[j][3];
        }
    }
    __syncthreads();

    if (t < 64) {
        const int r    = t >> 2;
        const int s4   = t & 3;
        const int grow = row0 + r;

        float vals[25];
        float sum = 0.0f;
        #pragma unroll
        for (int j = 0; j < 25; j++) {
            int c = s4 + 4 * j;
            float v = ys[r * 104 + c] + w2b[c] + xs[r * 108 + c];
            vals[j] = v;  sum += v;
        }
        sum += __shfl_xor_sync(0xffffffffu, sum, 1);
        sum += __shfl_xor_sync(0xffffffffu, sum, 2);
        const float mean = sum * (1.0f / DM);

        float v2 = 0.0f;
        #pragma unroll
        for (int j = 0; j < 25; j++) {
            float d = vals[j] - mean;
            v2 = fmaf(d, d, v2);
        }
        v2 += __shfl_xor_sync(0xffffffffu, v2, 1);
        v2 += __shfl_xor_sync(0xffffffffu, v2, 2);
        const float inv = rsqrtf(v2 * (1.0f / DM) + 1e-5f);

        #pragma unroll
        for (int j = 0; j < 25; j++) {
            int c = s4 + 4 * j;
            outp[grow * DM + c] = (vals[j] - mean) * inv * ln2g[c] + ln2b[c];
        }
    }
}

// ---------------------------------------------------------------------------
extern "C" void kernel_launch(void* const* d_in, const int* in_sizes, int n_in,
                              void* d_out, int out_size)
{
    (void)in_sizes; (void)n_in; (void)out_size;
    const float* edges = (const float*)d_in[0];
    const float* wq    = (const float*)d_in[1];
    const float* bq    = (const float*)d_in[2];
    const float* wk    = (const float*)d_in[3];
    const float* bk    = (const float*)d_in[4];
    const float* wv    = (const float*)d_in[5];
    const float* bv    = (const float*)d_in[6];
    const float* qcw   = (const float*)d_in[7];
    const float* qcb   = (const float*)d_in[8];
    const float* kcw   = (const float*)d_in[9];
    const float* kcb   = (const float*)d_in[10];
    const float* vcw   = (const float*)d_in[11];
    const float* vcb   = (const float*)d_in[12];
    const float* fcw   = (const float*)d_in[13];
    const float* fcb   = (const float*)d_in[14];
    const float* ln1g  = (const float*)d_in[15];
    const float* ln1b  = (const float*)d_in[16];
    const float* w1w   = (const float*)d_in[17];
    const float* w1b   = (const float*)d_in[18];
    const float* w2w   = (const float*)d_in[19];
    const float* w2b   = (const float*)d_in[20];
    const float* ln2g  = (const float*)d_in[21];
    const float* ln2b  = (const float*)d_in[22];

    static const int smem_qkv = 69120;
    static const int smem_fc  = 95744;
    static const int smem_mlp = 213504;
    cudaFuncSetAttribute(qkv_gemm,  cudaFuncAttributeMaxDynamicSharedMemorySize, smem_qkv);
    cudaFuncSetAttribute(fc_tc,     cudaFuncAttributeMaxDynamicSharedMemorySize, smem_fc);
    cudaFuncSetAttribute(mlp_fused, cudaFuncAttributeMaxDynamicSharedMemorySize, smem_mlp);

    qkv_gemm<<<dim3(64, 16), 384, smem_qkv>>>(edges, wq, bq, wk, bk, wv, bv,
                                              qcw, qcb, kcw, kcb, vcw, vcb);
    attn_kernel<<<NSB / 8, 256>>>();
    fc_tc<<<dim3(16, KSPLIT), 256, smem_fc>>>(fcw);
    mlp_fused<<<64, 256, smem_mlp>>>(edges, fcb, ln1g, ln1b,
                                     w1w, w1b, w2w, w2b, ln2g, ln2b,
                                     (float*)d_out);
}

// round 13
// speedup vs baseline: 1.1105x; 1.1105x over previous
#include <cuda_runtime.h>

// Problem constants
#define DM    100
#define NSDK  2048
#define ROWS  1024        // SZ_B * L
#define DI_   400
#define KSPLIT 8
#define PART_STRIDE (ROWS * DM)
#define LOG2E 1.44269504088896340736f

// Scratch (device globals — no allocation)
__device__ float g_att[ROWS * NSDK];          // attention output (tf32 bits)
__device__ float g_part[KSPLIT * PART_STRIDE];// fc split-K partials

// ---------------------------------------------------------------------------
// helpers
// ---------------------------------------------------------------------------
__device__ __forceinline__ float ex2(float x) {     // raw MUFU.EX2
    float y;
    asm("ex2.approx.f32 %0, %1;" : "=f"(y) : "f"(x));
    return y;
}

__device__ __forceinline__ unsigned f2tf(float v) {
    unsigned r;
    asm("cvt.rna.tf32.f32 %0, %1;" : "=r"(r) : "f"(v));
    return r;
}

__device__ __forceinline__ void cvt4_inplace(float* p) {
    float4 v = *(float4*)p;
    unsigned u0 = f2tf(v.x), u1 = f2tf(v.y), u2 = f2tf(v.z), u3 = f2tf(v.w);
    uint4 w = make_uint4(u0, u1, u2, u3);
    *(uint4*)p = w;
}

__device__ __forceinline__ void mma_tf32(float c[4],
                                         unsigned a0, unsigned a1, unsigned a2, unsigned a3,
                                         unsigned b0, unsigned b1) {
    asm("mma.sync.aligned.m16n8k8.row.col.f32.tf32.tf32.f32 "
        "{%0,%1,%2,%3},{%4,%5,%6,%7},{%8,%9},{%0,%1,%2,%3};"
        : "+f"(c[0]), "+f"(c[1]), "+f"(c[2]), "+f"(c[3])
        : "r"(a0), "r"(a1), "r"(a2), "r"(a3), "r"(b0), "r"(b1));
}

__device__ __forceinline__ unsigned sa(const void* p) {
    return (unsigned)__cvta_generic_to_shared(p);
}
__device__ __forceinline__ void cp16(unsigned d, const void* s) {
    asm volatile("cp.async.ca.shared.global [%0], [%1], 16;" :: "r"(d), "l"(s));
}
__device__ __forceinline__ void cp16z(unsigned d, const void* s, int srcbytes) {
    asm volatile("cp.async.ca.shared.global [%0], [%1], 16, %2;"
                 :: "r"(d), "l"(s), "r"(srcbytes));
}
#define CP_COMMIT    asm volatile("cp.async.commit_group;")
#define CP_WAIT_1    asm volatile("cp.async.wait_group 1;")
#define CP_WAIT_0    asm volatile("cp.async.wait_group 0;")
#define CP_WAIT_ALL  asm volatile("cp.async.wait_all;")

// ---------------------------------------------------------------------------
// K1: FUSED QKV projection + attention (R11-best). K=100 smem-resident,
// tf32 in place. Pair-blocked softmax; g_att written pre-rounded to tf32.
// Block 384 thr (12 warps). grid (64, 16). Dynamic smem 69120 B.
// ---------------------------------------------------------------------------
__global__ __launch_bounds__(384) void qkv_attn(
        const float* __restrict__ edges,
        const float* __restrict__ wq, const float* __restrict__ bq,
        const float* __restrict__ wk, const float* __restrict__ bk,
        const float* __restrict__ wv, const float* __restrict__ bv,
        const float* __restrict__ qcw, const float* __restrict__ qcb,
        const float* __restrict__ kcw, const float* __restrict__ kcb,
        const float* __restrict__ vcw, const float* __restrict__ vcb)
{
    extern __shared__ float smem[];
    float* A = smem;                 // [64][108]
    float* B = smem + 64 * 108;      // [96][108]
    float* sq = smem;                // union: [32 batches][2 w][32 h], pitch 68
    float* sk = smem + 2176;
    float* sv = smem + 4352;

    const int t    = threadIdx.x;
    const int lane = t & 31;
    const int wid  = t >> 5;
    const int tig  = lane & 3;
    const int gid  = lane >> 2;

    const int ns   = blockIdx.x;
    const int row0 = blockIdx.y * 64;

    const int pw = wid >> 2;
    const int m0 = (wid & 3) * 16;

    for (int idx = t; idx < 1600; idx += 384) {
        int r = idx / 25, q = idx - r * 25;
        cp16(sa(A + r * 108 + q * 4), edges + (row0 + r) * DM + q * 4);
    }
    for (int idx = t; idx < 2400; idx += 384) {
        int rr = idx / 25, q = idx - rr * 25;
        int p = rr >> 5, n = rr & 31;
        const float* W = (p == 0) ? wq : (p == 1) ? wk : wv;
        cp16(sa(B + rr * 108 + q * 4), W + (ns * 32 + n) * DM + q * 4);
    }
    CP_COMMIT; CP_WAIT_ALL;

    for (int idx = t; idx < 1600; idx += 384) {
        int r = idx / 25, q = idx - r * 25;
        cvt4_inplace(A + r * 108 + q * 4);
    }
    for (int idx = t; idx < 2400; idx += 384) {
        int rr = idx / 25, q = idx - rr * 25;
        cvt4_inplace(B + rr * 108 + q * 4);
    }
    for (int idx = t; idx < 160; idx += 384) {
        float* ptr = smem + idx * 108 + 100;
        ptr[0] = 0.0f; ptr[1] = 0.0f; ptr[2] = 0.0f; ptr[3] = 0.0f;
    }
    __syncthreads();

    const unsigned* Au = (const unsigned*)A;
    const unsigned* Bu = (const unsigned*)B;

    float acc[4][4] = {};
    #pragma unroll
    for (int ks = 0; ks < 13; ks++) {
        const int k0 = ks * 8;
        unsigned a0 = Au[(m0 + gid) * 108 + k0 + tig];
        unsigned a1 = Au[(m0 + gid + 8) * 108 + k0 + tig];
        unsigned a2 = Au[(m0 + gid) * 108 + k0 + tig + 4];
        unsigned a3 = Au[(m0 + gid + 8) * 108 + k0 + tig + 4];
        #pragma unroll
        for (int j = 0; j < 4; j++) {
            const int brow = pw * 32 + j * 8 + gid;
            unsigned b0 = Bu[brow * 108 + k0 + tig];
            unsigned b1 = Bu[brow * 108 + k0 + tig + 4];
            mma_tf32(acc[j], a0, a1, a2, a3, b0, b1);
        }
    }

    __syncthreads();   // all mma smem reads done before union overwrite

    {
        const float scale = (pw == 0) ? *qcw : (pw == 1) ? *kcw : *vcw;
        const float shift = (pw == 0) ? *qcb : (pw == 1) ? *kcb : *vcb;
        const float* bias = (pw == 0) ? bq : (pw == 1) ? bk : bv;
        float* sX = (pw == 0) ? sq : (pw == 1) ? sk : sv;

        #pragma unroll
        for (int j = 0; j < 4; j++) {
            const int col = j * 8 + 2 * tig;           // even
            const float b0v = bias[ns * 32 + col];
            const float b1v = bias[ns * 32 + col + 1];
            #pragma unroll
            for (int i = 0; i < 2; i++) {
                const int r = m0 + gid + i * 8;        // local row 0..63
                const int off = (r >> 1) * 68 + (r & 1) * 16 + (col >> 1);
                sX[off]      = fmaf(scale, acc[j][2 * i] + b0v, shift);
                sX[off + 32] = fmaf(scale, acc[j][2 * i + 1] + b1v, shift);
            }
        }
    }
    __syncthreads();

    // pair-blocked softmax, 1024 pairs
    unsigned* g_att_u = (unsigned*)g_att;
    for (int p = t; p < 1024; p += 384) {
        const int bloc = p >> 5;
        const int r    = p & 31;
        const int w    = r >> 4;
        const int h0   = r & 15;
        const int base = bloc * 68;
        const int wb   = base + w * 32;

        const float q0 = sq[wb + h0] * LOG2E;
        const float q1 = sq[wb + h0 + 16] * LOG2E;
        const float* Kw = sk + wb;
        const float* Vw = sv + wb;

        float Z0 = 0.0f, A0 = 0.0f, Z1 = 0.0f, A1 = 0.0f;
        #pragma unroll
        for (int c = 0; c < 8; c++) {
            float4 k4 = *(const float4*)(Kw + 4 * c);
            float4 v4 = *(const float4*)(Vw + 4 * c);
            float e;
            e = ex2(q0 * k4.x); Z0 += e; A0 = fmaf(e, v4.x, A0);
            e = ex2(q1 * k4.x); Z1 += e; A1 = fmaf(e, v4.x, A1);
            e = ex2(q0 * k4.y); Z0 += e; A0 = fmaf(e, v4.y, A0);
            e = ex2(q1 * k4.y); Z1 += e; A1 = fmaf(e, v4.y, A1);
            e = ex2(q0 * k4.z); Z0 += e; A0 = fmaf(e, v4.z, A0);
            e = ex2(q1 * k4.z); Z1 += e; A1 = fmaf(e, v4.z, A1);
            e = ex2(q0 * k4.w); Z0 += e; A0 = fmaf(e, v4.w, A0);
            e = ex2(q1 * k4.w); Z1 += e; A1 = fmaf(e, v4.w, A1);
        }

        const float k00 = sk[base + h0];
        const float k01 = sk[base + 32 + h0];
        const float v00 = sv[base + h0];
        const float v01 = sv[base + 32 + h0];
        const float k10 = sk[base + h0 + 16];
        const float k11 = sk[base + 32 + h0 + 16];
        const float v10 = sv[base + h0 + 16];
        const float v11 = sv[base + 32 + h0 + 16];

        const float e00 = ex2(q0 * k00);
        const float e01 = ex2(q0 * k01);
        const float e10 = ex2(q1 * k10);
        const float e11 = ex2(q1 * k11);

        const float pd0 = w ? e01 : e00;
        const float vd0 = w ? v01 : v00;
        const float pd1 = w ? e11 : e10;
        const float vd1 = w ? v11 : v10;

        Z0 = Z0 - pd0 + e00 + e01;
        A0 = A0 - pd0 * vd0 + e00 * v00 + e01 * v01;
        Z1 = Z1 - pd1 + e10 + e11;
        A1 = A1 - pd1 * vd1 + e10 * v10 + e11 * v11;

        const float o0 = __fdividef(A0, Z0);
        const float o1 = __fdividef(A1, Z1);

        const int dk   = 2 * h0 + w;
        const int grow = row0 + 2 * bloc;
        g_att_u[grow * NSDK + ns * 32 + dk]         = f2tf(o0);
        g_att_u[(grow + 1) * NSDK + ns * 32 + dk]   = f2tf(o1);
    }
}

// ---------------------------------------------------------------------------
// K2: fc GEMM split-K (tf32), double-buffered cp.async. A already tf32.
// 256 threads (8 warps: 4M x 2N). Tile 64(M) x 112(N), 4 chunks of K=64.
// grid (16, 8). Dynamic smem 95744 B.
// ---------------------------------------------------------------------------
__global__ __launch_bounds__(256) void fc_tc(const float* __restrict__ fcw)
{
    extern __shared__ float smem[];

    const int t    = threadIdx.x;
    const int lane = t & 31;
    const int wid  = t >> 5;
    const int tig  = lane & 3;
    const int gid  = lane >> 2;

    const int row0 = blockIdx.x * 64;
    const int ks   = blockIdx.y;

    const int wm0 = (wid >> 1) * 16;
    const int wn0 = (wid & 1) * 56;

    float acc[7][4] = {};

    auto load_chunk = [&](int c, int buf) {
        const int kb = ks * 256 + c * 64;
        float* A = smem + buf * 11968;
        float* B = A + 4352;
        for (int idx = t; idx < 1024; idx += 256) {
            int r = idx >> 4, q = idx & 15;
            cp16(sa(A + r * 68 + q * 4), g_att + (row0 + r) * NSDK + kb + q * 4);
        }
        for (int idx = t; idx < 1792; idx += 256) {
            int r = idx >> 4, q = idx & 15;
            int rc = (r < DM) ? r : (DM - 1);
            cp16z(sa(B + r * 68 + q * 4), fcw + rc * NSDK + kb + q * 4,
                  (r < DM) ? 16 : 0);
        }
        CP_COMMIT;
    };

    load_chunk(0, 0);

    for (int c = 0; c < 4; c++) {
        if (c < 3) load_chunk(c + 1, (c + 1) & 1);
        if (c < 3) { CP_WAIT_1; } else { CP_WAIT_0; }

        float* Af = smem + (c & 1) * 11968;
        float* Bf = Af + 4352;

        for (int idx = t; idx < 1792; idx += 256) {
            int r = idx >> 4, q = idx & 15;
            cvt4_inplace(Bf + r * 68 + q * 4);
        }
        __syncthreads();

        const unsigned* A = (const unsigned*)Af;
        const unsigned* B = (const unsigned*)Bf;

        #pragma unroll
        for (int kss = 0; kss < 8; kss++) {
            const int k0 = kss * 8;
            unsigned a0 = A[(wm0 + gid) * 68 + k0 + tig];
            unsigned a1 = A[(wm0 + gid + 8) * 68 + k0 + tig];
            unsigned a2 = A[(wm0 + gid) * 68 + k0 + tig + 4];
            unsigned a3 = A[(wm0 + gid + 8) * 68 + k0 + tig + 4];
            #pragma unroll
            for (int j = 0; j < 7; j++) {
                const int brow = wn0 + j * 8 + gid;
                unsigned b0 = B[brow * 68 + k0 + tig];
                unsigned b1 = B[brow * 68 + k0 + tig + 4];
                mma_tf32(acc[j], a0, a1, a2, a3, b0, b1);
            }
        }
        __syncthreads();
    }

    #pragma unroll
    for (int j = 0; j < 7; j++) {
        const int col = wn0 + j * 8 + 2 * tig;
        if (col < DM) {
            int r0 = row0 + wm0 + gid;
            *(float2*)&g_part[ks * PART_STRIDE + r0 * DM + col] =
                make_float2(acc[j][0], acc[j][1]);
            *(float2*)&g_part[ks * PART_STRIDE + (r0 + 8) * DM + col] =
                make_float2(acc[j][2], acc[j][3]);
        }
    }
}

// ---------------------------------------------------------------------------
// K3: FUSED tail, now 512 threads (16 warps) to double cp.async issue rate.
// partials-reduce + LN1 + MLP-l1(relu) + MLP-l2 + LN2 -> out.
// 16 rows/block, grid 64. smem layout unchanged (213504 B).
// ---------------------------------------------------------------------------
__global__ __launch_bounds__(512) void mlp_fused(
        const float* __restrict__ edges, const float* __restrict__ fcb,
        const float* __restrict__ ln1g,  const float* __restrict__ ln1b,
        const float* __restrict__ w1,    const float* __restrict__ w1b,
        const float* __restrict__ w2,    const float* __restrict__ w2b,
        const float* __restrict__ ln2g,  const float* __restrict__ ln2b,
        float* __restrict__ outp)
{
    extern __shared__ float smem[];
    float* xs  = smem;            // [16][108]  LN1 output (k-pad zeroed)
    float* hs  = smem + 1728;     // [16][420]  hidden (cols 400..415 zeroed)
    float* sR0 = smem + 8448;
    float* sR1 = smem + 30912;

    const int t    = threadIdx.x;
    const int lane = t & 31;
    const int wid  = t >> 5;      // 0..15
    const int tig  = lane & 3;
    const int gid  = lane >> 2;
    const int row0 = blockIdx.x * 16;

    auto cp_w1 = [&](int chunk, float* R) {
        const int rows = chunk ? 192 : 208;
        const int base = chunk * 208;
        for (int idx = t; idx < rows * 26; idx += 512) {
            int r = idx / 26, q = idx - r * 26;
            if (q < 25)
                cp16(sa(R + r * 108 + q * 4), w1 + (base + r) * DM + q * 4);
            else
                cp16z(sa(R + r * 108 + 100), w1, 0);
        }
        CP_COMMIT;
    };

    auto cp_w2 = [&](int chunk, float* R) {
        const int kbase = chunk * 208;
        for (int idx = t; idx < 104 * 52; idx += 512) {
            int r = idx / 52, q = idx - r * 52;
            int k = kbase + q * 4;
            int ok = (r < DM) && (k + 4 <= DI_);
            cp16z(sa(R + r * 212 + q * 4),
                  w2 + (ok ? r * DI_ + k : 0), ok ? 16 : 0);
        }
        CP_COMMIT;
    };

    cp_w1(0, sR0);                                   // G0

    for (int idx = t; idx < 1600; idx += 512) {
        int r = idx / 100, c = idx - r * 100;
        int grow = row0 + r;
        float v = fcb[c] + edges[grow * DM + c];
        #pragma unroll
        for (int s = 0; s < KSPLIT; s++)
            v += g_part[s * PART_STRIDE + grow * DM + c];
        xs[r * 108 + c] = v;
    }
    __syncthreads();

    if (t < 64) {
        const int r = t >> 2, s4 = t & 3;
        float vals[25];
        float sum = 0.0f;
        #pragma unroll
        for (int j = 0; j < 25; j++) {
            float v = xs[r * 108 + s4 + 4 * j];
            vals[j] = v;  sum += v;
        }
        sum += __shfl_xor_sync(0xffffffffu, sum, 1);
        sum += __shfl_xor_sync(0xffffffffu, sum, 2);
        const float mean = sum * (1.0f / DM);
        float v2 = 0.0f;
        #pragma unroll
        for (int j = 0; j < 25; j++) {
            float d = vals[j] - mean;
            v2 = fmaf(d, d, v2);
        }
        v2 += __shfl_xor_sync(0xffffffffu, v2, 1);
        v2 += __shfl_xor_sync(0xffffffffu, v2, 2);
        const float inv = rsqrtf(v2 * (1.0f / DM) + 1e-5f);
        #pragma unroll
        for (int j = 0; j < 25; j++) {
            int c = s4 + 4 * j;
            xs[r * 108 + c] = (vals[j] - mean) * inv * ln1g[c] + ln1b[c];
        }
        if (s4 == 0) {
            xs[r * 108 + 100] = 0.0f; xs[r * 108 + 101] = 0.0f;
            xs[r * 108 + 102] = 0.0f; xs[r * 108 + 103] = 0.0f;
        }
    }

    cp_w1(1, sR1);                                   // G1
    CP_WAIT_1; __syncthreads();                      // G0 done

    // layer1: frags distributed over 16 warps (warp handles wid, wid+16, ...)
    auto layer1_chunk = [&](int chunk, const float* R) {
        const int nfr = chunk ? 24 : 26;
        const int nmy = (nfr - wid + 15) >> 4;       // 0..2
        const int nbg = chunk * 208;
        float acc[2][4] = {};
        #pragma unroll
        for (int ks = 0; ks < 13; ks++) {
            const int k0 = ks * 8;
            unsigned a0 = f2tf(xs[gid * 108 + k0 + tig]);
            unsigned a1 = f2tf(xs[(gid + 8) * 108 + k0 + tig]);
            unsigned a2 = f2tf(xs[gid * 108 + k0 + tig + 4]);
            unsigned a3 = f2tf(xs[(gid + 8) * 108 + k0 + tig + 4]);
            #pragma unroll
            for (int j = 0; j < 2; j++) {
                if (j < nmy) {
                    int brow = (wid + 16 * j) * 8 + gid;
                    unsigned b0 = f2tf(R[brow * 108 + k0 + tig]);
                    unsigned b1 = f2tf(R[brow * 108 + k0 + tig + 4]);
                    mma_tf32(acc[j], a0, a1, a2, a3, b0, b1);
                }
            }
        }
        #pragma unroll
        for (int j = 0; j < 2; j++) {
            if (j < nmy) {
                int cg = nbg + (wid + 16 * j) * 8 + 2 * tig;
                float bb0 = w1b[cg], bb1 = w1b[cg + 1];
                hs[gid * 420 + cg]           = fmaxf(acc[j][0] + bb0, 0.0f);
                hs[gid * 420 + cg + 1]       = fmaxf(acc[j][1] + bb1, 0.0f);
                hs[(gid + 8) * 420 + cg]     = fmaxf(acc[j][2] + bb0, 0.0f);
                hs[(gid + 8) * 420 + cg + 1] = fmaxf(acc[j][3] + bb1, 0.0f);
            }
        }
    };

    layer1_chunk(0, sR0);
    __syncthreads();
    cp_w2(0, sR0);                                   // G2
    CP_WAIT_1; __syncthreads();                      // G1 done
    layer1_chunk(1, sR1);
    if (t < 256) {                                   // zero hs k-pad 400..415
        int r = t >> 4, c = 400 + (t & 15);
        hs[r * 420 + c] = 0.0f;
    }
    __syncthreads();
    cp_w2(1, sR1);                                   // G3
    CP_WAIT_1; __syncthreads();                      // G2 done

    // layer2: 13 n-frags (104 cols / 8), warps 0..12 one frag each
    const int active2 = (wid < 13);
    float l2acc[4] = {};
    auto layer2_chunk = [&](int chunk, const float* R) {
        if (!active2) return;
        #pragma unroll 2
        for (int ks = 0; ks < 26; ks++) {
            const int k0 = ks * 8;
            const int kk = chunk * 208 + k0;
            unsigned a0 = f2tf(hs[gid * 420 + kk + tig]);
            unsigned a1 = f2tf(hs[(gid + 8) * 420 + kk + tig]);
            unsigned a2 = f2tf(hs[gid * 420 + kk + tig + 4]);
            unsigned a3 = f2tf(hs[(gid + 8) * 420 + kk + tig + 4]);
            const int brow = wid * 8 + gid;
            unsigned b0 = f2tf(R[brow * 212 + k0 + tig]);
            unsigned b1 = f2tf(R[brow * 212 + k0 + tig + 4]);
            mma_tf32(l2acc, a0, a1, a2, a3, b0, b1);
        }
    };

    layer2_chunk(0, sR0);
    CP_WAIT_0; __syncthreads();                      // G3 done
    layer2_chunk(1, sR1);

    __syncthreads();
    float* ys = sR0;                                 // [16][104]
    if (active2) {
        int col = wid * 8 + 2 * tig;
        ys[gid * 104 + col]           = l2acc[0];
        ys[gid * 104 + col + 1]       = l2acc[1];
        ys[(gid + 8) * 104 + col]     = l2acc[2];
        ys[(gid + 8) * 104 + col + 1] = l2acc[3];
    }
    __syncthreads();

    if (t < 64) {
        const int r    = t >> 2;
        const int s4   = t & 3;
        const int grow = row0 + r;

        float vals[25];
        float sum = 0.0f;
        #pragma unroll
        for (int j = 0; j < 25; j++) {
            int c = s4 + 4 * j;
            float v = ys[r * 104 + c] + w2b[c] + xs[r * 108 + c];
            vals[j] = v;  sum += v;
        }
        sum += __shfl_xor_sync(0xffffffffu, sum, 1);
        sum += __shfl_xor_sync(0xffffffffu, sum, 2);
        const float mean = sum * (1.0f / DM);

        float v2 = 0.0f;
        #pragma unroll
        for (int j = 0; j < 25; j++) {
            float d = vals[j] - mean;
            v2 = fmaf(d, d, v2);
        }
        v2 += __shfl_xor_sync(0xffffffffu, v2, 1);
        v2 += __shfl_xor_sync(0xffffffffu, v2, 2);
        const float inv = rsqrtf(v2 * (1.0f / DM) + 1e-5f);

        #pragma unroll
        for (int j = 0; j < 25; j++) {
            int c = s4 + 4 * j;
            outp[grow * DM + c] = (vals[j] - mean) * inv * ln2g[c] + ln2b[c];
        }
    }
}

// ---------------------------------------------------------------------------
extern "C" void kernel_launch(void* const* d_in, const int* in_sizes, int n_in,
                              void* d_out, int out_size)
{
    (void)in_sizes; (void)n_in; (void)out_size;
    const float* edges = (const float*)d_in[0];
    const float* wq    = (const float*)d_in[1];
    const float* bq    = (const float*)d_in[2];
    const float* wk    = (const float*)d_in[3];
    const float* bk    = (const float*)d_in[4];
    const float* wv    = (const float*)d_in[5];
    const float* bv    = (const float*)d_in[6];
    const float* qcw   = (const float*)d_in[7];
    const float* qcb   = (const float*)d_in[8];
    const float* kcw   = (const float*)d_in[9];
    const float* kcb   = (const float*)d_in[10];
    const float* vcw   = (const float*)d_in[11];
    const float* vcb   = (const float*)d_in[12];
    const float* fcw   = (const float*)d_in[13];
    const float* fcb   = (const float*)d_in[14];
    const float* ln1g  = (const float*)d_in[15];
    const float* ln1b  = (const float*)d_in[16];
    const float* w1w   = (const float*)d_in[17];
    const float* w1b   = (const float*)d_in[18];
    const float* w2w   = (const float*)d_in[19];
    const float* w2b   = (const float*)d_in[20];
    const float* ln2g  = (const float*)d_in[21];
    const float* ln2b  = (const float*)d_in[22];

    static const int smem_qkv = 69120;
    static const int smem_fc  = 95744;
    static const int smem_mlp = 213504;
    cudaFuncSetAttribute(qkv_attn,  cudaFuncAttributeMaxDynamicSharedMemorySize, smem_qkv);
    cudaFuncSetAttribute(fc_tc,     cudaFuncAttributeMaxDynamicSharedMemorySize, smem_fc);
    cudaFuncSetAttribute(mlp_fused, cudaFuncAttributeMaxDynamicSharedMemorySize, smem_mlp);

    qkv_attn<<<dim3(64, 16), 384, smem_qkv>>>(edges, wq, bq, wk, bk, wv, bv,
                                              qcw, qcb, kcw, kcb, vcw, vcb);
    fc_tc<<<dim3(16, KSPLIT), 256, smem_fc>>>(fcw);
    mlp_fused<<<64, 512, smem_mlp>>>(edges, fcb, ln1g, ln1b,
                                     w1w, w1b, w2w, w2b, ln2g, ln2b,
                                     (float*)d_out);
}